// round 2
// baseline (speedup 1.0000x reference)
#include <cuda_runtime.h>
#include <cstdint>

typedef unsigned long long ull;

#define NB 512
#define NT 512
#define NC 64
#define WPB 4   // warps (= batches) per block

// Per-batch (log_denominator - log_numerator) scratch.
__device__ float g_partial[NB];

__device__ __forceinline__ ull fma2(ull a, ull b, ull c) {
    ull d;
    asm("fma.rn.f32x2 %0, %1, %2, %3;" : "=l"(d) : "l"(a), "l"(b), "l"(c));
    return d;
}
__device__ __forceinline__ ull add2(ull a, ull b) {
    ull d;
    asm("add.rn.f32x2 %0, %1, %2;" : "=l"(d) : "l"(a), "l"(b));
    return d;
}
__device__ __forceinline__ ull pack2(float x, float y) {
    ull d;
    asm("mov.b64 %0, {%1, %2};" : "=l"(d) : "f"(x), "f"(y));
    return d;
}
__device__ __forceinline__ void unpack2(ull v, float& x, float& y) {
    asm("mov.b64 {%0, %1}, %2;" : "=f"(x), "=f"(y) : "l"(v));
}

__global__ void __launch_bounds__(32 * WPB, 1) crf_forward(
    const float* __restrict__ emissions,   // [B, T, C]
    const int*   __restrict__ tags,        // [B, T]
    const int*   __restrict__ mask,        // [B, T]
    const float* __restrict__ trans,       // [C, C]
    const float* __restrict__ startt,      // [C]
    const float* __restrict__ endt)        // [C]
{
    // Double-buffered p, stored as duplicated pairs: entry i = (p[i], p[i]) so a
    // broadcast LDS.64 feeds fma.rn.f32x2 directly.
    __shared__ __align__(16) ull pbuf[WPB][2][NC];

    const int wid  = threadIdx.x >> 5;
    const int lane = threadIdx.x & 31;
    const int b    = blockIdx.x * WPB + wid;
    const int j0   = lane * 2;           // this lane owns output columns j0, j0+1

    // ---- E = exp(transitions), columns j0/j0+1, resident in registers ----
    ull e2[NC];
#pragma unroll
    for (int i = 0; i < NC; i++) {
        float2 tv = *reinterpret_cast<const float2*>(&trans[i * NC + j0]);
        e2[i] = pack2(__expf(tv.x), __expf(tv.y));
    }

    const int*   tg   = &tags[(size_t)b * NT];
    const int*   mk   = &mask[(size_t)b * NT];
    const float* em_b = &emissions[(size_t)b * NT * NC];

    // ---- joint score (log numerator), lane-strided over t ----
    float num = 0.f;
    int   cnt = 0;
    for (int t = lane; t < NT; t += 32) {
        int tt = tg[t];
        int m  = mk[t];
        cnt += m;
        if (t > 0 && m) {
            int tp = tg[t - 1];
            num += trans[tp * NC + tt] + em_b[(size_t)t * NC + tt];
        }
    }
    cnt = __reduce_add_sync(0xffffffffu, cnt);
#pragma unroll
    for (int o = 16; o > 0; o >>= 1)
        num += __shfl_down_sync(0xffffffffu, num, o);
    if (lane == 0) {
        int t0 = tg[0];
        num += startt[t0] + em_b[t0];
        num += endt[tg[cnt - 1]];
    }

    // ---- forward init: lp0 = start + emit[0]; to p-domain ----
    float2 em0 = *reinterpret_cast<const float2*>(&em_b[j0]);
    float  ax  = startt[j0]     + em0.x;
    float  ay  = startt[j0 + 1] + em0.y;
    // max over warp via positive-float-bits-monotonic-as-int trick
    float mpair = fmaxf(ax, ay);
    float m0    = __int_as_float(__reduce_max_sync(0xffffffffu, __float_as_int(mpair)));
    float logZ  = m0;
    float px = __expf(ax - m0);
    float py = __expf(ay - m0);
    int   cur = 0;
    reinterpret_cast<float4*>(pbuf[wid][0])[lane] = make_float4(px, px, py, py);
    __syncwarp();

    // ---- main recurrence ----
    float2 emn   = *reinterpret_cast<const float2*>(&em_b[NC + j0]);  // t = 1
    int    since = 0;
    for (int t = 1; t < NT; t++) {
        float2 emc = emn;
        if (t + 1 < NT)
            emn = *reinterpret_cast<const float2*>(&em_b[(size_t)(t + 1) * NC + j0]);
        int mupd = mk[t];  // uniform across warp

        const ull* pb = pbuf[wid][cur];
        ull q0 = 0, q1 = 0, q2 = 0, q3 = 0;
#pragma unroll
        for (int i = 0; i < NC; i += 4) {
            q0 = fma2(pb[i + 0], e2[i + 0], q0);
            q1 = fma2(pb[i + 1], e2[i + 1], q1);
            q2 = fma2(pb[i + 2], e2[i + 2], q2);
            q3 = fma2(pb[i + 3], e2[i + 3], q3);
        }
        ull q = add2(add2(q0, q1), add2(q2, q3));

        if (mupd) {
            float qx, qy;
            unpack2(q, qx, qy);
            float ux = qx * __expf(emc.x);
            float uy = qy * __expf(emc.y);
            // renormalize every 4 updates (worst-case growth ~e^14/step < e^88/4)
            if (++since >= 4) {
                since = 0;
                float mp = fmaxf(ux, uy);
                float mm = __int_as_float(
                    __reduce_max_sync(0xffffffffu, __float_as_int(mp)));
                float inv = __frcp_rn(mm);
                ux *= inv;
                uy *= inv;
                logZ += __logf(mm);
            }
            cur ^= 1;
            reinterpret_cast<float4*>(pbuf[wid][cur])[lane] =
                make_float4(ux, ux, uy, uy);
        }
        __syncwarp();
    }

    // ---- log denominator: logZ + log(sum_j p[j] * exp(end[j])) ----
    const float* pf = reinterpret_cast<const float*>(pbuf[wid][cur]);
    float fx = pf[4 * lane];      // p[j0]   (duplicated-pair .x)
    float fy = pf[4 * lane + 2];  // p[j0+1]
    float2 et = *reinterpret_cast<const float2*>(&endt[j0]);
    float contrib = fx * __expf(et.x) + fy * __expf(et.y);
#pragma unroll
    for (int o = 16; o > 0; o >>= 1)
        contrib += __shfl_down_sync(0xffffffffu, contrib, o);

    if (lane == 0) {
        float denom = logZ + __logf(contrib);
        g_partial[b] = denom - num;
    }
}

__global__ void crf_reduce(float* __restrict__ out) {
    __shared__ float s[NB];
    int t = threadIdx.x;
    s[t] = g_partial[t];
    __syncthreads();
#pragma unroll
    for (int o = NB / 2; o > 0; o >>= 1) {
        if (t < o) s[t] += s[t + o];
        __syncthreads();
    }
    if (t == 0) out[0] = s[0] * (1.0f / (float)NB);
}

extern "C" void kernel_launch(void* const* d_in, const int* in_sizes, int n_in,
                              void* d_out, int out_size) {
    const float* emissions = (const float*)d_in[0];
    const int*   tags      = (const int*)d_in[1];
    const int*   mask      = (const int*)d_in[2];
    const float* trans     = (const float*)d_in[3];
    const float* startt    = (const float*)d_in[4];
    const float* endt      = (const float*)d_in[5];
    (void)in_sizes; (void)n_in; (void)out_size;

    crf_forward<<<NB / WPB, 32 * WPB>>>(emissions, tags, mask, trans, startt, endt);
    crf_reduce<<<1, NB>>>((float*)d_out);
}

// round 3
// speedup vs baseline: 1.4884x; 1.4884x over previous
#include <cuda_runtime.h>
#include <cstdint>

typedef unsigned long long ull;

#define NB 512
#define NT 512
#define NC 64
#define WPB 4
#define FULLMASK 0xffffffffu

__device__ float    g_partial[NB];
__device__ unsigned g_done;   // self-resetting completion counter

static __device__ __forceinline__ ull fma2(ull a, ull b, ull c) {
    ull d; asm("fma.rn.f32x2 %0,%1,%2,%3;" : "=l"(d) : "l"(a), "l"(b), "l"(c)); return d;
}
static __device__ __forceinline__ ull add2(ull a, ull b) {
    ull d; asm("add.rn.f32x2 %0,%1,%2;" : "=l"(d) : "l"(a), "l"(b)); return d;
}
static __device__ __forceinline__ ull pack2(float x, float y) {
    ull d; asm("mov.b64 %0,{%1,%2};" : "=l"(d) : "f"(x), "f"(y)); return d;
}
static __device__ __forceinline__ void unpack2(ull v, float& x, float& y) {
    asm("mov.b64 {%0,%1},%2;" : "=f"(x), "=f"(y) : "l"(v));
}

// One forward-recurrence step. Emission exps are issued BEFORE the FMA block
// (independent of q, MUFU latency hides under FMA issue). Renorm (every 4th
// step) happens before the store so it costs no extra STS/sync.
#define CRF_STEP(EMC, MBIT, DO_RENORM) do {                                      \
    float ex_ = __expf((EMC).x), ey_ = __expf((EMC).y);                          \
    const ulonglong2* pb_ = (const ulonglong2*)pbuf[wid][cur];                   \
    ull q0_ = 0, q1_ = 0, q2_ = 0, q3_ = 0;                                      \
    _Pragma("unroll")                                                            \
    for (int g_ = 0; g_ < 16; g_++) {                                            \
        ulonglong2 v_ = pb_[2 * g_];                                             \
        ulonglong2 w_ = pb_[2 * g_ + 1];                                         \
        q0_ = fma2(v_.x, e2[4 * g_ + 0], q0_);                                   \
        q1_ = fma2(v_.y, e2[4 * g_ + 1], q1_);                                   \
        q2_ = fma2(w_.x, e2[4 * g_ + 2], q2_);                                   \
        q3_ = fma2(w_.y, e2[4 * g_ + 3], q3_);                                   \
    }                                                                            \
    ull qq_ = add2(add2(q0_, q1_), add2(q2_, q3_));                              \
    float qx_, qy_; unpack2(qq_, qx_, qy_);                                      \
    if (MBIT) { px = qx_ * ex_; py = qy_ * ey_; }                                \
    if (DO_RENORM) {                                                             \
        /* p values are strictly positive -> int-bit max is valid */             \
        float mm_ = __int_as_float(                                              \
            __reduce_max_sync(FULLMASK, __float_as_int(fmaxf(px, py))));         \
        float inv_ = __frcp_rn(mm_);                                             \
        px *= inv_; py *= inv_; logZ += __logf(mm_);                             \
    }                                                                            \
    cur ^= 1;                                                                    \
    ((float4*)pbuf[wid][cur])[lane] = make_float4(px, px, py, py);               \
    __syncwarp();                                                                \
} while (0)

__global__ void __launch_bounds__(32 * WPB, 1) crf_forward(
    const float* __restrict__ emissions,   // [B, T, C]
    const int*   __restrict__ tags,        // [B, T]
    const int*   __restrict__ mask,        // [B, T]
    const float* __restrict__ trans,       // [C, C]
    const float* __restrict__ startt,      // [C]
    const float* __restrict__ endt,        // [C]
    float*       __restrict__ out)         // [1]
{
    // Double-buffered p, duplicated pairs: entry i = (p[i], p[i]) so LDS.128
    // broadcast feeds fma.rn.f32x2 directly (2 pairs / load).
    __shared__ __align__(16) ull pbuf[WPB][2][NC];
    __shared__ bool s_last;

    const int wid  = threadIdx.x >> 5;
    const int lane = threadIdx.x & 31;
    const int b    = blockIdx.x * WPB + wid;
    const int j0   = lane * 2;

    const int*   tg = tags + (size_t)b * NT;
    const int*   mk = mask + (size_t)b * NT;
    const float* em = emissions + (size_t)b * NT * NC;

    // ---- issue all long-latency startup loads first ----
    float2 em0  = *(const float2*)(em + j0);
    float2 emP0 = *(const float2*)(em + (size_t)1 * NC + j0);
    float2 emP1 = *(const float2*)(em + (size_t)2 * NC + j0);
    float2 emP2 = *(const float2*)(em + (size_t)3 * NC + j0);
    int4   mk03 = *(const int4*)(mk);       // mask[0..3]
    int4   mc   = *(const int4*)(mk + 4);   // first group's mask (t=4..7)
    float2 emc0 = *(const float2*)(em + (size_t)4 * NC + j0);
    float2 emc1 = *(const float2*)(em + (size_t)5 * NC + j0);
    float2 emc2 = *(const float2*)(em + (size_t)6 * NC + j0);
    float2 emc3 = *(const float2*)(em + (size_t)7 * NC + j0);
    float2 st2  = *(const float2*)(startt + j0);
    float2 et2  = *(const float2*)(endt + j0);

    // ---- E = exp(transitions), this lane's two columns, in registers ----
    ull e2[NC];
#pragma unroll
    for (int i = 0; i < NC; i++) {
        float2 tv = *(const float2*)(trans + i * NC + j0);
        e2[i] = pack2(__expf(tv.x), __expf(tv.y));
    }

    // ---- joint score (log numerator), lane-strided over t ----
    float num = 0.f;
    int   cnt = 0;
#pragma unroll 4
    for (int t = lane; t < NT; t += 32) {
        int tt = tg[t];
        int m  = mk[t];
        cnt += m;
        if (t > 0 && m)
            num += trans[tg[t - 1] * NC + tt] + em[(size_t)t * NC + tt];
    }
    cnt = __reduce_add_sync(FULLMASK, cnt);
#pragma unroll
    for (int o = 16; o > 0; o >>= 1)
        num += __shfl_down_sync(FULLMASK, num, o);
    if (lane == 0) {
        int t0 = tg[0];
        num += st2.x * 0.f + startt[t0] + em[t0] + endt[tg[cnt - 1]];
    }

    // ---- init t = 0 (sign-safe fmax via shfl tree; values may be negative) ----
    float ax = st2.x + em0.x, ay = st2.y + em0.y;
    float m0 = fmaxf(ax, ay);
#pragma unroll
    for (int o = 16; o > 0; o >>= 1)
        m0 = fmaxf(m0, __shfl_xor_sync(FULLMASK, m0, o));
    float logZ = m0;
    float px = __expf(ax - m0);
    float py = __expf(ay - m0);
    int   cur = 0;
    ((float4*)pbuf[wid][0])[lane] = make_float4(px, px, py, py);
    __syncwarp();

    // ---- prologue t = 1..3 (renorm on the last one) ----
    CRF_STEP(emP0, mk03.y, false);
    CRF_STEP(emP1, mk03.z, false);
    CRF_STEP(emP2, mk03.w, true);

    // ---- main loop: aligned groups of 4, next group prefetched (MLP=5) ----
#pragma unroll 1
    for (int t0 = 4; t0 < NT; t0 += 4) {
        float2 en0 = emc0, en1 = emc1, en2 = emc2, en3 = emc3;
        int4   mn  = mc;
        if (t0 + 4 < NT) {
            const float* p4 = em + (size_t)(t0 + 4) * NC + j0;
            en0 = *(const float2*)(p4);
            en1 = *(const float2*)(p4 + NC);
            en2 = *(const float2*)(p4 + 2 * NC);
            en3 = *(const float2*)(p4 + 3 * NC);
            mn  = *(const int4*)(mk + t0 + 4);
        }
        CRF_STEP(emc0, mc.x, false);
        CRF_STEP(emc1, mc.y, false);
        CRF_STEP(emc2, mc.z, false);
        CRF_STEP(emc3, mc.w, true);
        emc0 = en0; emc1 = en1; emc2 = en2; emc3 = en3; mc = mn;
    }

    // ---- log denominator & per-batch loss ----
    float contrib = px * __expf(et2.x) + py * __expf(et2.y);
#pragma unroll
    for (int o = 16; o > 0; o >>= 1)
        contrib += __shfl_down_sync(FULLMASK, contrib, o);
    if (lane == 0)
        g_partial[b] = logZ + __logf(contrib) - num;

    // ---- fused final reduction: last block to finish reduces all 512 ----
    __syncthreads();
    if (threadIdx.x == 0) {
        __threadfence();
        unsigned prev = atomicAdd(&g_done, 1u);
        s_last = (prev == gridDim.x - 1);
    }
    __syncthreads();
    if (s_last && wid == 0) {
        __threadfence();
        float s = 0.f;
        const float4* gp = (const float4*)g_partial;
#pragma unroll
        for (int k = 0; k < 4; k++) {
            float4 v = __ldcg(gp + lane + 32 * k);
            s += (v.x + v.y) + (v.z + v.w);
        }
#pragma unroll
        for (int o = 16; o > 0; o >>= 1)
            s += __shfl_down_sync(FULLMASK, s, o);
        if (lane == 0) {
            out[0] = s * (1.0f / (float)NB);
            g_done = 0;   // reset for the next graph replay (deterministic)
        }
    }
}

extern "C" void kernel_launch(void* const* d_in, const int* in_sizes, int n_in,
                              void* d_out, int out_size) {
    const float* emissions = (const float*)d_in[0];
    const int*   tags      = (const int*)d_in[1];
    const int*   mask      = (const int*)d_in[2];
    const float* trans     = (const float*)d_in[3];
    const float* startt    = (const float*)d_in[4];
    const float* endt      = (const float*)d_in[5];
    (void)in_sizes; (void)n_in; (void)out_size;

    crf_forward<<<NB / WPB, 32 * WPB>>>(emissions, tags, mask, trans, startt,
                                        endt, (float*)d_out);
}